// round 6
// baseline (speedup 1.0000x reference)
#include <cuda_runtime.h>

#define NN 10000
#define HID 16
#define LAB 7
#define KC 32             // k per chunk
#define RPB 64            // rows per block
#define PITCH4 9          // float4 pitch (odd -> conflict-free LDS.128)
#define NCHT 313          // ceil(10000/32)
#define KSPLIT 4
#define DEPTH 4

__device__ int g_is64;
__device__ __align__(16) float g_deg_src[NN];
__device__ __align__(16) float g_deg_dst[NN];
__device__ __align__(16) float g_norm_src[NN];
__device__ __align__(16) float g_norm_dst[NN];
__device__ __align__(16) float g_h[NN * HID];   // features @ W1 (unnormalized)
__device__ __align__(16) float g_agg1[NN * HID];
__device__ __align__(16) float g_h2[NN * 8];
__device__ __align__(16) float g_agg2[NN * 8];

// ---------- helpers ----------
__device__ __forceinline__ unsigned long long pack2(float x) {
    unsigned long long r;
    asm("mov.b64 %0, {%1, %1};" : "=l"(r) : "f"(x));
    return r;
}
__device__ __forceinline__ void fma2(unsigned long long& d, unsigned long long a,
                                     unsigned long long b) {
    asm("fma.rn.f32x2 %0, %1, %2, %0;" : "+l"(d) : "l"(a), "l"(b));
}
__device__ __forceinline__ float2 unpack2(unsigned long long v) {
    float2 u;
    asm("mov.b64 {%0, %1}, %2;" : "=f"(u.x), "=f"(u.y) : "l"(v));
    return u;
}
__device__ __forceinline__ void redg_v4(float* p, float4 v) {
    unsigned long long gp;
    asm("cvta.to.global.u64 %0, %1;" : "=l"(gp) : "l"(p));
    asm volatile("red.global.add.v4.f32 [%0], {%1, %2, %3, %4};"
                 ::"l"(gp), "f"(v.x), "f"(v.y), "f"(v.z), "f"(v.w) : "memory");
}
__device__ __forceinline__ void redg_f32(float* p, float v) {
    unsigned long long gp;
    asm("cvta.to.global.u64 %0, %1;" : "=l"(gp) : "l"(p));
    asm volatile("red.global.add.f32 [%0], %1;" ::"l"(gp), "f"(v) : "memory");
}
__device__ __forceinline__ void cp16(unsigned smem_dst, const void* gsrc, int sz) {
    asm volatile("cp.async.cg.shared.global [%0], [%1], 16, %2;"
                 ::"r"(smem_dst), "l"(gsrc), "r"(sz));
}
__device__ __forceinline__ int eidx(const void* p, int e, int is64) {
    int v = ((const int*)p)[is64 ? 2 * e : e];
    return min(max(v, 0), NN - 1);
}

// ---------- K0: detect dtype + zero scratch ----------
__global__ void k_init(const int* __restrict__ src) {
    int i = blockIdx.x * blockDim.x + threadIdx.x;
    if (i == 0) {
        int all_odd_zero = 1;
        for (int t = 1; t < 256; t += 2)
            if (src[t] != 0) { all_odd_zero = 0; break; }
        g_is64 = all_odd_zero;
    }
    int stride = gridDim.x * blockDim.x;
    for (int t = i; t < NN; t += stride) { g_deg_src[t] = 0.f; g_deg_dst[t] = 0.f; }
    for (int t = i; t < NN * HID; t += stride) { g_h[t] = 0.f; g_agg1[t] = 0.f; }
    for (int t = i; t < NN * 8; t += stride) g_agg2[t] = 0.f;
}

// ---------- K1: degrees ----------
__global__ void k_deg(const void* __restrict__ src, const void* __restrict__ dst, int nE) {
    int e = blockIdx.x * blockDim.x + threadIdx.x;
    if (e >= nE) return;
    int is64 = g_is64;
    redg_f32(&g_deg_src[eidx(src, e, is64)], 1.f);
    redg_f32(&g_deg_dst[eidx(dst, e, is64)], 1.f);
}

// ---------- K2: norms ----------
__global__ void k_norm() {
    int n = blockIdx.x * blockDim.x + threadIdx.x;
    if (n >= NN) return;
    g_norm_src[n] = rsqrtf(fmaxf(g_deg_src[n], 1.f));
    g_norm_dst[n] = rsqrtf(fmaxf(g_deg_dst[n], 1.f));
}

// ---------- K3: g_h += features @ W1 (K-split partials) ----------
// 4-stage cp.async ring, KC=32. One __syncthreads per chunk:
//   wait_group DEPTH-2 -> sync -> compute(c) -> issue(c+3)+commit.
// Compute: warp w owns quad w of the 8-quad chunk; lane owns rows
// {lane, lane+32}. Per k: 4 uniform LDS.128 (W broadcast) + 16 FFMA2.
__global__ void __launch_bounds__(256, 2)
k_gemm1(const float* __restrict__ feat, const float* __restrict__ W1) {
    __shared__ __align__(16) float4 sF[DEPTH][RPB * PITCH4];   // 4 x 9216 B
    __shared__ __align__(16) float4 sW[DEPTH][KC * HID / 4];   // 4 x 2048 B

    const int tid = threadIdx.x;
    const int w = tid >> 5;
    const int lane = tid & 31;
    const int rowBase = blockIdx.x * RPB;
    const int ks = blockIdx.y;
    const int ch0 = (ks * NCHT) / KSPLIT;
    const int ch1 = ((ks + 1) * NCHT) / KSPLIT;
    const int nch = ch1 - ch0;

    const int fr = tid >> 3;          // staging row 0..31 (+32)
    const int fq = tid & 7;           // staging quad in row
    const float4* W14 = (const float4*)W1;

    auto issue = [&](int c) {
        if (c < nch) {
            const int b = c & (DEPTH - 1);
            const int c0 = (ch0 + c) * KC;
            const int gc = c0 + 4 * fq;
            const int okc = (gc < NN);
#pragma unroll
            for (int i = 0; i < 2; i++) {
                int r = fr + 32 * i;
                int gr = rowBase + r;
                int ok = (okc && gr < NN);
                const float* s = feat + (size_t)min(gr, NN - 1) * NN + min(gc, NN - 4);
                cp16((unsigned)__cvta_generic_to_shared(&sF[b][r * PITCH4 + fq]), s,
                     ok ? 16 : 0);
            }
            if (tid < KC * HID / 4) {
                int gq = c0 * 4 + tid;
                int ok = (gq < NN * 4);
                cp16((unsigned)__cvta_generic_to_shared(&sW[b][tid]),
                     W14 + min(gq, NN * 4 - 1), ok ? 16 : 0);
            }
        }
        asm volatile("cp.async.commit_group;" ::: "memory");
    };

    unsigned long long a0[8], a1[8];
#pragma unroll
    for (int i = 0; i < 8; i++) { a0[i] = 0ull; a1[i] = 0ull; }

    issue(0); issue(1); issue(2);

    for (int c = 0; c < nch; c++) {
        const int b = c & (DEPTH - 1);
        asm volatile("cp.async.wait_group %0;" ::"n"(DEPTH - 2) : "memory");
        __syncthreads();

        const float* wB = (const float*)sW[b];
        float4 f0 = sF[b][lane * PITCH4 + w];
        float4 f1 = sF[b][(lane + 32) * PITCH4 + w];
        const float fa0[4] = {f0.x, f0.y, f0.z, f0.w};
        const float fa1[4] = {f1.x, f1.y, f1.z, f1.w};
#pragma unroll
        for (int m = 0; m < 4; m++) {
            const ulonglong2* wr = (const ulonglong2*)(wB + (w * 4 + m) * HID);
            ulonglong2 q0 = wr[0], q1 = wr[1], q2 = wr[2], q3 = wr[3];
            unsigned long long p0 = pack2(fa0[m]);
            unsigned long long p1 = pack2(fa1[m]);
            fma2(a0[0], q0.x, p0); fma2(a0[1], q0.y, p0);
            fma2(a0[2], q1.x, p0); fma2(a0[3], q1.y, p0);
            fma2(a0[4], q2.x, p0); fma2(a0[5], q2.y, p0);
            fma2(a0[6], q3.x, p0); fma2(a0[7], q3.y, p0);
            fma2(a1[0], q0.x, p1); fma2(a1[1], q0.y, p1);
            fma2(a1[2], q1.x, p1); fma2(a1[3], q1.y, p1);
            fma2(a1[4], q2.x, p1); fma2(a1[5], q2.y, p1);
            fma2(a1[6], q3.x, p1); fma2(a1[7], q3.y, p1);
        }
        issue(c + 3);
    }
    __syncthreads();

    // cross-warp reduce; reuse sF (needs 8192 floats, sF = 9216 float4-equiv OK)
    float* red = (float*)sF;
#pragma unroll
    for (int i = 0; i < 8; i++) {
        float2 u0 = unpack2(a0[i]);
        float2 u1 = unpack2(a1[i]);
        red[((2 * i) * 8 + w) * RPB + lane] = u0.x;
        red[((2 * i + 1) * 8 + w) * RPB + lane] = u0.y;
        red[((2 * i) * 8 + w) * RPB + lane + 32] = u1.x;
        red[((2 * i + 1) * 8 + w) * RPB + lane + 32] = u1.y;
    }
    __syncthreads();
    {
        const int r = tid >> 2;
        const int qc = tid & 3;
        const int gr = rowBase + r;
        if (gr < NN) {
            float s[4] = {0.f, 0.f, 0.f, 0.f};
#pragma unroll
            for (int ww = 0; ww < 8; ww++)
#pragma unroll
                for (int m = 0; m < 4; m++)
                    s[m] += red[((qc * 4 + m) * 8 + ww) * RPB + r];
            redg_v4(&g_h[(size_t)gr * HID + qc * 4],
                    make_float4(s[0], s[1], s[2], s[3]));
        }
    }
}

// ---------- K4: scatter layer 1 (norm_src applied per edge) ----------
__global__ void k_scatter1(const void* __restrict__ src, const void* __restrict__ dst,
                           int nE) {
    int e = blockIdx.x * blockDim.x + threadIdx.x;
    if (e >= nE) return;
    int is64 = g_is64;
    int s = eidx(src, e, is64), d = eidx(dst, e, is64);
    float f = g_norm_src[s];
    const float4* hp = (const float4*)(g_h + (size_t)s * HID);
    float* ap = g_agg1 + (size_t)d * HID;
#pragma unroll
    for (int q = 0; q < 4; q++) {
        float4 v = hp[q];
        v.x *= f; v.y *= f; v.z *= f; v.w *= f;
        redg_v4(ap + 4 * q, v);
    }
}

// ---------- K5: h1 = relu(agg1*norm_dst + b1); h2 = (h1*norm_src) @ W2 ----------
__global__ void k_layer2(const float* __restrict__ b1, const float* __restrict__ W2) {
    int n = blockIdx.x * blockDim.x + threadIdx.x;
    if (n >= NN) return;
    float nd = g_norm_dst[n], ns = g_norm_src[n];
    float h1[HID];
    const float4* ap = (const float4*)(g_agg1 + (size_t)n * HID);
#pragma unroll
    for (int q = 0; q < 4; q++) {
        float4 v = ap[q];
        h1[4 * q + 0] = fmaxf(fmaf(v.x, nd, __ldg(&b1[4 * q + 0])), 0.f);
        h1[4 * q + 1] = fmaxf(fmaf(v.y, nd, __ldg(&b1[4 * q + 1])), 0.f);
        h1[4 * q + 2] = fmaxf(fmaf(v.z, nd, __ldg(&b1[4 * q + 2])), 0.f);
        h1[4 * q + 3] = fmaxf(fmaf(v.w, nd, __ldg(&b1[4 * q + 3])), 0.f);
    }
    float o[LAB];
#pragma unroll
    for (int j = 0; j < LAB; j++) o[j] = 0.f;
#pragma unroll
    for (int k = 0; k < HID; k++) {
        float hv = h1[k];
#pragma unroll
        for (int j = 0; j < LAB; j++) o[j] = fmaf(hv, __ldg(&W2[k * LAB + j]), o[j]);
    }
#pragma unroll
    for (int j = 0; j < LAB; j++) g_h2[n * 8 + j] = ns * o[j];
    g_h2[n * 8 + 7] = 0.f;
}

// ---------- K6: scatter layer 2 ----------
__global__ void k_scatter2(const void* __restrict__ src, const void* __restrict__ dst,
                           int nE) {
    int e = blockIdx.x * blockDim.x + threadIdx.x;
    if (e >= nE) return;
    int is64 = g_is64;
    int s = eidx(src, e, is64), d = eidx(dst, e, is64);
    const float4* hp = (const float4*)(g_h2 + (size_t)s * 8);
    float4 v0 = hp[0], v1 = hp[1];
    float* ap = g_agg2 + (size_t)d * 8;
    redg_v4(ap, v0);
    redg_v4(ap + 4, v1);
}

// ---------- K7: finalize ----------
__global__ void k_final(const float* __restrict__ b2, float* __restrict__ out) {
    int i = blockIdx.x * blockDim.x + threadIdx.x;
    if (i >= NN * LAB) return;
    int n = i / LAB, j = i - n * LAB;
    out[i] = fmaf(g_agg2[n * 8 + j], g_norm_dst[n], __ldg(&b2[j]));
}

extern "C" void kernel_launch(void* const* d_in, const int* in_sizes, int n_in,
                              void* d_out, int out_size) {
    const float* feat = (const float*)d_in[0];
    const void* src = d_in[1];
    const void* dst = d_in[2];
    const float* W1 = (const float*)d_in[3];
    const float* b1 = (const float*)d_in[4];
    const float* W2 = (const float*)d_in[5];
    const float* b2 = (const float*)d_in[6];
    int nE = in_sizes[1];
    float* out = (float*)d_out;

    int eb = (nE + 255) / 256;

    k_init<<<256, 256>>>((const int*)src);
    k_deg<<<eb, 256>>>(src, dst, nE);
    k_norm<<<(NN + 255) / 256, 256>>>();
    dim3 g1((NN + RPB - 1) / RPB, KSPLIT);     // 157 x 4 = 628 blocks
    k_gemm1<<<g1, 256>>>(feat, W1);
    k_scatter1<<<eb, 256>>>(src, dst, nE);
    k_layer2<<<(NN + 255) / 256, 256>>>(b1, W2);
    k_scatter2<<<eb, 256>>>(src, dst, nE);
    k_final<<<(NN * LAB + 255) / 256, 256>>>(b2, out);
}